// round 16
// baseline (speedup 1.0000x reference)
#include <cuda_runtime.h>
#include <cstdint>

// MeanAggregator: out[r,:] = mean over UNIQUE neighbors c of row r of embed[c,:]
// row_idx sorted ascending. D = 300 floats = 75 float4 = 1200 B per row.
// R16: block-per-row cp.async.bulk gather. Warp 0 dedups (match_any) into a
// compacted unique list; thread 0 issues 1200B bulk async copies (L2 -> SMEM,
// bypassing L1tex) in 16-row stages, 2-stage mbarrier pipeline; 75 threads
// reduce each stage from smem in fixed order (deterministic).

#define AGG_D4    75
#define ROW_BYTES 1200
#define AGG_MAXL  96           // fast-path cap (L ~ Poisson(32), max ~70)
#define AGG_MAXB  65536
#define NB        16           // rows per stage
#define NSTAGE    2

__device__ int g_row_start[AGG_MAXB + 1];

// K1: vectorized CSR diff-scatter (4 boundaries/thread, shfl for prev).
__global__ void build_row_starts(const int* __restrict__ row_idx, int E, int B) {
    const int t    = blockIdx.x * blockDim.x + threadIdx.x;
    const int lane = threadIdx.x & 31;
    const int i0   = t * 4;
    if (i0 > E) return;

    if (i0 > 0 && i0 + 4 <= E) {
        int4 q = *reinterpret_cast<const int4*>(row_idx + i0);
        int prevv = __shfl_up_sync(0xffffffffu, q.w, 1);
        if (lane == 0) prevv = row_idx[i0 - 1];
        int vals[4] = { q.x, q.y, q.z, q.w };
        int p = prevv;
        #pragma unroll
        for (int k = 0; k < 4; ++k) {
            int cur = vals[k];
            for (int v = p + 1; v <= cur; ++v) g_row_start[v] = i0 + k;
            p = cur;
        }
    } else {
        #pragma unroll
        for (int k = 0; k < 4; ++k) {
            int i = i0 + k;
            if (i > E) break;
            if (i == 0) {
                int cur = row_idx[0];
                for (int v = 0; v <= cur; ++v) g_row_start[v] = 0;
            } else if (i == E) {
                int prev = row_idx[E - 1];
                for (int v = prev + 1; v <= B; ++v) g_row_start[v] = E;
            } else {
                int prev = row_idx[i - 1];
                int cur  = row_idx[i];
                for (int v = prev + 1; v <= cur; ++v) g_row_start[v] = i;
            }
        }
    }
}

// ---- PTX helpers ----
__device__ __forceinline__ uint32_t smem_u32(const void* p) {
    uint32_t a;
    asm("{ .reg .u64 t; cvta.to.shared.u64 t, %1; cvt.u32.u64 %0, t; }"
        : "=r"(a) : "l"(p));
    return a;
}
__device__ __forceinline__ void mbar_init(uint32_t a, uint32_t cnt) {
    asm volatile("mbarrier.init.shared.b64 [%0], %1;" :: "r"(a), "r"(cnt) : "memory");
}
__device__ __forceinline__ void mbar_expect_tx(uint32_t a, uint32_t tx) {
    asm volatile("mbarrier.arrive.expect_tx.shared.b64 _, [%0], %1;"
                 :: "r"(a), "r"(tx) : "memory");
}
__device__ __forceinline__ void bulk_ld(uint32_t dst, const void* src,
                                        uint32_t bytes, uint32_t mbar) {
    asm volatile(
        "cp.async.bulk.shared::cta.global.mbarrier::complete_tx::bytes "
        "[%0], [%1], %2, [%3];"
        :: "r"(dst), "l"(src), "r"(bytes), "r"(mbar) : "memory");
}
__device__ __forceinline__ void mbar_wait(uint32_t a, uint32_t ph) {
    asm volatile(
        "{\n\t.reg .pred P;\n\t"
        "W%=:\n\t"
        "mbarrier.try_wait.parity.acquire.cta.shared::cta.b64 P, [%0], %1, 0x989680;\n\t"
        "@P bra D%=;\n\t"
        "bra W%=;\n\t"
        "D%=:\n\t}"
        :: "r"(a), "r"(ph) : "memory");
}

__global__ __launch_bounds__(128) void mean_agg_bulk(
    const int*   __restrict__ col_idx,
    const float* __restrict__ embed,     // [U, 300] f32
    float4*      __restrict__ out4,      // [B, 75]
    int B)
{
    const int r    = blockIdx.x;
    const int tid  = threadIdx.x;
    const int lane = tid & 31;

    __shared__ alignas(128) char stage[NSTAGE][NB * ROW_BYTES];
    __shared__ int s_raw[AGG_MAXL];
    __shared__ int s_uniq[AGG_MAXL];
    __shared__ int s_cnt;
    __shared__ alignas(8) unsigned long long s_mbar[NSTAGE];

    const int start = g_row_start[r];
    const int L     = g_row_start[r + 1] - start;

    const uint32_t mb0 = smem_u32(&s_mbar[0]);
    const uint32_t mb1 = smem_u32(&s_mbar[1]);
    const uint32_t st0 = smem_u32(&stage[0][0]);
    const uint32_t st1 = smem_u32(&stage[1][0]);

    if (tid == 0) { mbar_init(mb0, 1); mbar_init(mb1, 1); }

    // ---- warp 0: dedup (match_any) + compaction + prologue TMA issue ----
    if (tid < 32 && L <= AGG_MAXL) {
        const unsigned lt = (1u << lane) - 1u;
        const int j1 = 32 + lane, j2 = 64 + lane;
        int c0 = (lane < L) ? col_idx[start + lane] : -(lane + 1);
        int c1 = (j1   < L) ? col_idx[start + j1]   : -(lane + 1);
        int c2 = (j2   < L) ? col_idx[start + j2]   : -(lane + 1);
        s_raw[lane] = c0;
        if (j1 < L) s_raw[j1] = c1;
        if (j2 < L) s_raw[j2] = c2;
        __syncwarp();

        unsigned p0 = __match_any_sync(0xffffffffu, c0);
        bool v0 = (lane < L) && ((p0 & lt) == 0);
        unsigned m0 = __ballot_sync(0xffffffffu, v0);
        if (v0) s_uniq[__popc(m0 & lt)] = c0;
        int cnt = __popc(m0);
        if (L > 32) {
            unsigned p1 = __match_any_sync(0xffffffffu, c1);
            bool v1 = (j1 < L) && ((p1 & lt) == 0);
            if (v1) { for (int i = 0; i < 32; ++i) if (s_raw[i] == c1) { v1 = false; break; } }
            unsigned m1 = __ballot_sync(0xffffffffu, v1);
            if (v1) s_uniq[cnt + __popc(m1 & lt)] = c1;
            cnt += __popc(m1);
            if (L > 64) {
                unsigned p2 = __match_any_sync(0xffffffffu, c2);
                bool v2 = (j2 < L) && ((p2 & lt) == 0);
                if (v2) { for (int i = 0; i < 64; ++i) if (s_raw[i] == c2) { v2 = false; break; } }
                unsigned m2 = __ballot_sync(0xffffffffu, v2);
                if (v2) s_uniq[cnt + __popc(m2 & lt)] = c2;
                cnt += __popc(m2);
            }
        }
        if (lane == 0) s_cnt = cnt;
        __syncwarp();

        if (lane == 0) {
            const int Lu = cnt;
            const int nbatch = (Lu + NB - 1) / NB;
            for (int k = 0; k < nbatch && k < NSTAGE; ++k) {
                const int lo = k * NB;
                const int n  = min(NB, Lu - lo);
                const uint32_t bar = (k & 1) ? mb1 : mb0;
                const uint32_t dst = (k & 1) ? st1 : st0;
                mbar_expect_tx(bar, (uint32_t)(n * ROW_BYTES));
                for (int i = 0; i < n; ++i)
                    bulk_ld(dst + i * ROW_BYTES,
                            (const char*)embed + (size_t)s_uniq[lo + i] * ROW_BYTES,
                            ROW_BYTES, bar);
            }
        }
    }
    __syncthreads();

    if (L <= AGG_MAXL) {
        const int Lu     = s_cnt;
        const int nbatch = (Lu + NB - 1) / NB;
        float4 acc = make_float4(0.f, 0.f, 0.f, 0.f);
        int ph0 = 0, ph1 = 0;

        for (int k = 0; k < nbatch; ++k) {
            const int s = k & 1;
            if (s) { mbar_wait(mb1, ph1); ph1 ^= 1; }
            else   { mbar_wait(mb0, ph0); ph0 ^= 1; }

            const int n = min(NB, Lu - k * NB);
            if (tid < AGG_D4) {
                const char* base = stage[s];
                #pragma unroll 4
                for (int i = 0; i < n; ++i) {
                    float4 v = *reinterpret_cast<const float4*>(
                        base + i * ROW_BYTES + tid * 16);
                    acc.x += v.x; acc.y += v.y; acc.z += v.z; acc.w += v.w;
                }
            }
            __syncthreads();                       // all done reading stage[s]
            if (tid == 0 && k + NSTAGE < nbatch) { // refill stage[s]
                const int kk = k + NSTAGE;
                const int lo = kk * NB;
                const int n2 = min(NB, Lu - lo);
                const uint32_t bar = s ? mb1 : mb0;
                const uint32_t dst = s ? st1 : st0;
                mbar_expect_tx(bar, (uint32_t)(n2 * ROW_BYTES));
                for (int i = 0; i < n2; ++i)
                    bulk_ld(dst + i * ROW_BYTES,
                            (const char*)embed + (size_t)s_uniq[lo + i] * ROW_BYTES,
                            ROW_BYTES, bar);
            }
        }

        if (tid < AGG_D4) {
            const float inv = 1.0f / fmaxf((float)Lu, 1e-8f);
            out4[(size_t)r * AGG_D4 + tid] =
                make_float4(acc.x * inv, acc.y * inv, acc.z * inv, acc.w * inv);
        }
    } else {
        // Unreachable-for-this-data fallback: O(L^2) dedup, direct LDG accumulate.
        if (tid < AGG_D4) {
            float4 acc = make_float4(0.f, 0.f, 0.f, 0.f);
            int seen = 0;
            for (int j = 0; j < L; ++j) {
                int c = col_idx[start + j];
                bool first = true;
                for (int i = 0; i < j; ++i)
                    if (col_idx[start + i] == c) { first = false; break; }
                if (!first) continue;
                ++seen;
                float4 v = *(reinterpret_cast<const float4*>(
                    embed + (size_t)c * 300) + tid);
                acc.x += v.x; acc.y += v.y; acc.z += v.z; acc.w += v.w;
            }
            const float inv = 1.0f / fmaxf((float)seen, 1e-8f);
            out4[(size_t)r * AGG_D4 + tid] =
                make_float4(acc.x * inv, acc.y * inv, acc.z * inv, acc.w * inv);
        }
    }
}

extern "C" void kernel_launch(void* const* d_in, const int* in_sizes, int n_in,
                              void* d_out, int out_size) {
    const int*   row_idx = (const int*)  d_in[0];
    const int*   col_idx = (const int*)  d_in[1];
    const float* embed   = (const float*)d_in[2];
    float*       out     = (float*)      d_out;

    const int E = in_sizes[0];
    const int B = out_size / 300;

    const int k1_threads = E / 4 + 1;
    build_row_starts<<<(k1_threads + 255) / 256, 256>>>(row_idx, E, B);
    mean_agg_bulk<<<B, 128>>>(col_idx, embed, (float4*)out, B);
}

// round 17
// speedup vs baseline: 1.5664x; 1.5664x over previous
#include <cuda_runtime.h>
#include <cuda_bf16.h>

// MeanAggregator: out[r,:] = mean over UNIQUE neighbors c of row r of embed[c,:]
// row_idx sorted ascending. D = 300 floats = 75 float4.
// R17 = R15 chassis (warp per (row,slot), GATHER-ALL + SUBTRACT-DUPLICATES,
// dup detect deferred, plain LDG.128, vectorized int4 CSR build) with 128-thread
// CTAs (4 warps) for higher occupancy (48 vs 38 warps/SM at 40 regs) and
// finer-grained tail packing.

#define AGG_D4   75
#define AGG_MAXL 96            // fast-path cap: 3 chunks (L ~ Poisson(32), max ~70)
#define AGG_MAXB 65536
#define WARPS_PB 4             // 128-thread blocks

__device__ int g_row_start[AGG_MAXB + 1];

// K1: CSR row pointers by diff-scatter, vectorized: each thread owns boundaries
// i in [4t, 4t+4). Fast path: one int4 load + shfl_up for row_idx[4t-1]
// (lane 0 patches with a scalar load). Edges fall back to the scalar logic.
__global__ void build_row_starts(const int* __restrict__ row_idx, int E, int B) {
    const int t    = blockIdx.x * blockDim.x + threadIdx.x;
    const int lane = threadIdx.x & 31;
    const int i0   = t * 4;
    if (i0 > E) return;

    if (i0 > 0 && i0 + 4 <= E) {
        int4 q = *reinterpret_cast<const int4*>(row_idx + i0);
        int prevv = __shfl_up_sync(0xffffffffu, q.w, 1);
        if (lane == 0) prevv = row_idx[i0 - 1];
        int vals[4] = { q.x, q.y, q.z, q.w };
        int p = prevv;
        #pragma unroll
        for (int k = 0; k < 4; ++k) {
            int cur = vals[k];
            for (int v = p + 1; v <= cur; ++v) g_row_start[v] = i0 + k;
            p = cur;
        }
    } else {
        // shfl source above may be inactive here; pure scalar edge handling
        #pragma unroll
        for (int k = 0; k < 4; ++k) {
            int i = i0 + k;
            if (i > E) break;
            if (i == 0) {
                int cur = row_idx[0];
                for (int v = 0; v <= cur; ++v) g_row_start[v] = 0;
            } else if (i == E) {
                int prev = row_idx[E - 1];
                for (int v = prev + 1; v <= B; ++v) g_row_start[v] = E;
            } else {
                int prev = row_idx[i - 1];
                int cur  = row_idx[i];
                for (int v = prev + 1; v <= cur; ++v) g_row_start[v] = i;
            }
        }
    }
}

__global__ __launch_bounds__(WARPS_PB * 32) void mean_agg_kernel(
    const int*    __restrict__ col_idx,
    const float4* __restrict__ embed4,   // [U, 75]
    float4*       __restrict__ out4,     // [B, 75]
    int B)
{
    const int w    = threadIdx.x >> 5;
    const int lane = threadIdx.x & 31;
    const int gw   = blockIdx.x * WARPS_PB + w;   // global warp id
    const int r    = gw / 3;                      // row
    const int slot = gw - r * 3;                  // LDG slot 0/1/2
    if (r >= B) return;                           // warp-uniform

    const int  d4  = slot * 32 + lane;            // my float4 index in [0,75)
    const bool act = (d4 < AGG_D4);               // slot 2: lanes 0..10 only

    const int start = g_row_start[r];
    const int L     = g_row_start[r + 1] - start;

    __shared__ int s_col[WARPS_PB][AGG_MAXL];
    int* sc = s_col[w];

    float4 acc = make_float4(0.f, 0.f, 0.f, 0.f);
    const unsigned lt = (1u << lane) - 1u;
    const float4* __restrict__ e = embed4 + d4;
    int Lu = 0;

    if (L <= AGG_MAXL) {
        // ---- 3 independent coalesced chunk loads of col indices ----
        const int j1 = 32 + lane, j2 = 64 + lane;
        int c0 = (lane < L) ? col_idx[start + lane] : -(lane + 1);
        int c1 = (j1   < L) ? col_idx[start + j1]   : -(lane + 1);
        int c2 = (j2   < L) ? col_idx[start + j2]   : -(lane + 1);
        sc[lane] = c0;
        if (j1 < L) sc[j1] = c1;
        if (j2 < L) sc[j2] = c2;
        __syncwarp();

        // ---- main gather over ALL L entries (dups included): unroll-8,
        //      8 independent LDG.128 in flight, 1 LDG per neighbor ----
        if (act) {
            int j = 0;
            for (; j + 8 <= L; j += 8) {
                float4 v0 = e[(size_t)sc[j]     * AGG_D4];
                float4 v1 = e[(size_t)sc[j + 1] * AGG_D4];
                float4 v2 = e[(size_t)sc[j + 2] * AGG_D4];
                float4 v3 = e[(size_t)sc[j + 3] * AGG_D4];
                float4 v4 = e[(size_t)sc[j + 4] * AGG_D4];
                float4 v5 = e[(size_t)sc[j + 5] * AGG_D4];
                float4 v6 = e[(size_t)sc[j + 6] * AGG_D4];
                float4 v7 = e[(size_t)sc[j + 7] * AGG_D4];
                acc.x += (v0.x + v1.x + v2.x + v3.x) + (v4.x + v5.x + v6.x + v7.x);
                acc.y += (v0.y + v1.y + v2.y + v3.y) + (v4.y + v5.y + v6.y + v7.y);
                acc.z += (v0.z + v1.z + v2.z + v3.z) + (v4.z + v5.z + v6.z + v7.z);
                acc.w += (v0.w + v1.w + v2.w + v3.w) + (v4.w + v5.w + v6.w + v7.w);
            }
            for (; j + 4 <= L; j += 4) {
                float4 v0 = e[(size_t)sc[j]     * AGG_D4];
                float4 v1 = e[(size_t)sc[j + 1] * AGG_D4];
                float4 v2 = e[(size_t)sc[j + 2] * AGG_D4];
                float4 v3 = e[(size_t)sc[j + 3] * AGG_D4];
                acc.x += v0.x + v1.x + v2.x + v3.x;
                acc.y += v0.y + v1.y + v2.y + v3.y;
                acc.z += v0.z + v1.z + v2.z + v3.z;
                acc.w += v0.w + v1.w + v2.w + v3.w;
            }
            for (; j < L; ++j) {
                float4 v = e[(size_t)sc[j] * AGG_D4];
                acc.x += v.x; acc.y += v.y; acc.z += v.z; acc.w += v.w;
            }
        }

        // ---- duplicate detection AFTER the gather (all lanes participate) ----
        unsigned p0m = __match_any_sync(0xffffffffu, c0);
        bool d0 = (lane < L) && ((p0m & lt) != 0);
        bool d1 = false, d2 = false;
        if (L > 32) {
            unsigned p1m = __match_any_sync(0xffffffffu, c1);
            d1 = (j1 < L) && ((p1m & lt) != 0);
            if (!d1 && j1 < L) {
                for (int i = 0; i < 32; ++i)
                    if (sc[i] == c1) { d1 = true; break; }
            }
            if (L > 64) {
                unsigned p2m = __match_any_sync(0xffffffffu, c2);
                d2 = (j2 < L) && ((p2m & lt) != 0);
                if (!d2 && j2 < L) {
                    for (int i = 0; i < 64; ++i)
                        if (sc[i] == c2) { d2 = true; break; }
                }
            }
        }
        const unsigned m0 = __ballot_sync(0xffffffffu, d0);
        const unsigned m1 = __ballot_sync(0xffffffffu, d1);
        const unsigned m2 = __ballot_sync(0xffffffffu, d2);
        Lu = L - (__popc(m0) + __popc(m1) + __popc(m2));

        // ---- subtract duplicate occurrences (almost always all-zero masks) ----
        if (act && (m0 | m1 | m2)) {
            unsigned masks[3] = { m0, m1, m2 };
            #pragma unroll
            for (int k = 0; k < 3; ++k) {
                unsigned m = masks[k];
                while (m) {
                    int b = __ffs(m) - 1; m &= m - 1;
                    float4 v = e[(size_t)sc[k * 32 + b] * AGG_D4];
                    acc.x -= v.x; acc.y -= v.y; acc.z -= v.z; acc.w -= v.w;
                }
            }
        }
    } else {
        // Unreachable-for-this-data fallback: O(L^2) global dedup, direct accumulate.
        for (int j = 0; j < L; ++j) {
            int c = col_idx[start + j];
            bool valid = true;
            for (int i = 0; i < j; ++i)
                if (col_idx[start + i] == c) { valid = false; break; }
            if (!valid) continue;
            ++Lu;
            if (act) {
                float4 v = e[(size_t)c * AGG_D4];
                acc.x += v.x; acc.y += v.y; acc.z += v.z; acc.w += v.w;
            }
        }
    }

    if (act) {
        const float inv = 1.0f / fmaxf((float)Lu, 1e-8f);
        float4 t;
        t.x = acc.x * inv; t.y = acc.y * inv; t.z = acc.z * inv; t.w = acc.w * inv;
        out4[(size_t)r * AGG_D4 + d4] = t;
    }
}

extern "C" void kernel_launch(void* const* d_in, const int* in_sizes, int n_in,
                              void* d_out, int out_size) {
    const int*   row_idx = (const int*)  d_in[0];
    const int*   col_idx = (const int*)  d_in[1];
    const float* embed   = (const float*)d_in[2];
    float*       out     = (float*)      d_out;

    const int E = in_sizes[0];
    const int B = out_size / 300;

    const int k1_threads = E / 4 + 1;
    build_row_starts<<<(k1_threads + 255) / 256, 256>>>(row_idx, E, B);
    const int total_warps = 3 * B;
    mean_agg_kernel<<<(total_warps + WARPS_PB - 1) / WARPS_PB, WARPS_PB * 32>>>(
        col_idx, (const float4*)embed, (float4*)out, B);
}